// round 8
// baseline (speedup 1.0000x reference)
#include <cuda_runtime.h>
#include <math.h>
#include <stdint.h>

#define NEXP 8
#define TOPK 2
#define NTOK 16384
#define DDIM 512
#define HDIM 1408
#define MASSIGN (NTOK * TOPK)
#define RBLK (NTOK / 8)   // router blocks = 2048

// ---- scratch (device globals; no allocation) ----
__device__ int   g_count[NEXP];
__device__ int   g_off[NEXP + 1];
__device__ int   g_token[NEXP * NTOK];
__device__ float g_wgt[NEXP * NTOK];
__device__ int   g_aslot[NTOK * TOPK];           // (expert<<14)|slot per (token,k)
__device__ float g_usagep[RBLK * NEXP];          // per-router-block usage partials
__device__ float g_h[(size_t)MASSIGN * HDIM];    // ~184 MB hidden activations
__device__ float g_part[(size_t)MASSIGN * DDIM]; // ~64 MB weighted partial outputs

// ------------------------------------------------------------------
__device__ __forceinline__ float ftf32(float x) {
    uint32_t u;
    asm("cvt.rna.tf32.f32 %0, %1;" : "=r"(u) : "f"(x));
    return __uint_as_float(u);
}

__device__ __forceinline__ void mma_tf32(float c[4],
                                         uint32_t a0, uint32_t a1, uint32_t a2, uint32_t a3,
                                         uint32_t b0, uint32_t b1) {
    asm volatile(
        "mma.sync.aligned.m16n8k8.row.col.f32.tf32.tf32.f32 "
        "{%0,%1,%2,%3}, {%4,%5,%6,%7}, {%8,%9}, {%0,%1,%2,%3};\n"
        : "+f"(c[0]), "+f"(c[1]), "+f"(c[2]), "+f"(c[3])
        : "r"(a0), "r"(a1), "r"(a2), "r"(a3), "r"(b0), "r"(b1));
}

// ------------------------------------------------------------------
__global__ void k_zero() {
    int i = threadIdx.x;
    if (i < NEXP) g_count[i] = 0;
}

// ------------------------------------------------------------------
// Router: one warp per token. fp32 logits, softmax, top-2 (lowest index
// wins ties, matching lax.top_k), renormalize, scatter to expert lists.
// Per-block usage partials stored densely (no atomics -> deterministic).
// ------------------------------------------------------------------
__global__ void k_router(const float* __restrict__ x,
                         const float* __restrict__ rw) {
    int warp = threadIdx.x >> 5, lane = threadIdx.x & 31;
    int t = blockIdx.x * 8 + warp;
    __shared__ float susage[8][NEXP];

    float l[NEXP];
#pragma unroll
    for (int e = 0; e < NEXP; e++) l[e] = 0.f;

    const float* xr = x + (size_t)t * DDIM;
#pragma unroll 4
    for (int k = lane; k < DDIM; k += 32) {
        float xv = xr[k];
#pragma unroll
        for (int e = 0; e < NEXP; e++) l[e] += xv * rw[e * DDIM + k];
    }
#pragma unroll
    for (int o = 16; o > 0; o >>= 1)
#pragma unroll
        for (int e = 0; e < NEXP; e++)
            l[e] += __shfl_xor_sync(0xffffffffu, l[e], o);

    float mx = l[0];
#pragma unroll
    for (int e = 1; e < NEXP; e++) mx = fmaxf(mx, l[e]);
    float p[NEXP], s = 0.f;
#pragma unroll
    for (int e = 0; e < NEXP; e++) { p[e] = __expf(l[e] - mx); s += p[e]; }
    float inv = 1.f / s;
#pragma unroll
    for (int e = 0; e < NEXP; e++) p[e] *= inv;

    if (lane < NEXP) susage[warp][lane] = p[lane];

    if (lane == 0) {
        int i0 = 0;
#pragma unroll
        for (int e = 1; e < NEXP; e++) if (p[e] > p[i0]) i0 = e;
        int i1 = (i0 == 0) ? 1 : 0;
#pragma unroll
        for (int e = 0; e < NEXP; e++)
            if (e != i0 && p[e] > p[i1]) i1 = e;
        float sw = p[i0] + p[i1];
        float w0 = p[i0] / sw, w1 = p[i1] / sw;
        int s0 = atomicAdd(&g_count[i0], 1);
        g_token[i0 * NTOK + s0] = t; g_wgt[i0 * NTOK + s0] = w0;
        g_aslot[t * 2 + 0] = (i0 << 14) | s0;
        int s1 = atomicAdd(&g_count[i1], 1);
        g_token[i1 * NTOK + s1] = t; g_wgt[i1 * NTOK + s1] = w1;
        g_aslot[t * 2 + 1] = (i1 << 14) | s1;
    }
    __syncthreads();
    if (threadIdx.x < NEXP) {
        float u = 0.f;
#pragma unroll
        for (int w = 0; w < 8; w++) u += susage[w][threadIdx.x];   // fixed order
        g_usagep[blockIdx.x * NEXP + threadIdx.x] = u;
    }
}

// ------------------------------------------------------------------
// Offsets + aux loss. 256 threads: warp e reduces its expert's 2048
// partials in fixed order (deterministic bitwise aux_loss).
// ------------------------------------------------------------------
__global__ void k_offs(float* __restrict__ out, int out_size) {
    __shared__ float sus[NEXP];
    int tid = threadIdx.x, e = tid >> 5, lane = tid & 31;

    float u = 0.f;
    for (int b = lane; b < RBLK; b += 32)        // ascending fixed order
        u += g_usagep[b * NEXP + e];
#pragma unroll
    for (int o = 16; o > 0; o >>= 1)
        u += __shfl_xor_sync(0xffffffffu, u, o); // fixed butterfly tree
    if (lane == 0) sus[e] = u;
    __syncthreads();

    if (tid == 0) {
        int acc = 0;
        for (int i = 0; i < NEXP; i++) { g_off[i] = acc; acc += g_count[i]; }
        g_off[NEXP] = acc;
        float a = 0.f;
        for (int i = 0; i < NEXP; i++) {
            float uu = sus[i] * (1.f / (float)NTOK);
            a += uu * uu;
        }
        out[out_size - 1] = (float)NEXP * a * 0.01f;
    }
}

// ------------------------------------------------------------------
// tf32 mma grouped GEMM. BM=128, BN=64, BK=16, 256 thr = 8 warps
// (4M x 2N), warp tile 32x32 = 2x4 m16n8k8 atoms, double-buffered.
// Smem pitches 136 / 72 (== 8 mod 32) -> conflict-free fragment LDS.
// Static smem: up 35,840 B, down 26,624 B (under 48 KB cap).
// ------------------------------------------------------------------
#define BM 128
#define BN 64
#define BK 16
#define ALD 136   // BM + 8
#define BLD 72    // BN + 8

// up-proj: h[gm, j] = silu(x.w1^T) * (x.w3^T), per-expert token list
__global__ __launch_bounds__(256, 2) void k_up(const float* __restrict__ x,
                                               const float* __restrict__ w1,
                                               const float* __restrict__ w3) {
    int e   = blockIdx.z;
    int cnt = g_count[e];
    int m0  = blockIdx.x * BM;
    if (m0 >= cnt) return;
    int j0 = blockIdx.y * BN;

    __shared__ float As [2][BK * ALD];
    __shared__ float B1s[2][BK * BLD];
    __shared__ float B3s[2][BK * BLD];

    int tid  = threadIdx.x;
    int lane = tid & 31;
    int warp = tid >> 5;
    int wm   = (warp >> 1) * 32;      // warp M offset in tile
    int wn   = (warp & 1) * 32;       // warp N offset in tile
    int g    = lane >> 2;             // group id 0..7
    int tg   = lane & 3;              // thread-in-group 0..3

    // loaders (BK=16): A 128x16 -> 2 float4/thread, B 64x16 -> 1 float4/thread
    int alr = tid >> 1;               // A row 0..127
    int akf = (tid & 1) * 8;          // A k offset 0 or 8
    int blr = tid >> 2;               // B row 0..63
    int bkf = (tid & 3) * 4;          // B k offset 0,4,8,12

    int am  = m0 + alr;
    int tok = (am < cnt) ? g_token[e * NTOK + am] : g_token[e * NTOK];
    const float* xrow  = x  + (size_t)tok * DDIM;
    const float* w1row = w1 + (size_t)e * HDIM * DDIM + (size_t)(j0 + blr) * DDIM;
    const float* w3row = w3 + (size_t)e * HDIM * DDIM + (size_t)(j0 + blr) * DDIM;

    float acc1[2][4][4], acc3[2][4][4];
#pragma unroll
    for (int i = 0; i < 2; i++)
#pragma unroll
        for (int j = 0; j < 4; j++)
#pragma unroll
            for (int c = 0; c < 4; c++) { acc1[i][j][c] = 0.f; acc3[i][j][c] = 0.f; }

    float4 av0, av1, b1v, b3v;

    // prologue: tile 0
    av0 = *(const float4*)(xrow + akf);
    av1 = *(const float4*)(xrow + akf + 4);
    b1v = *(const float4*)(w1row + bkf);
    b3v = *(const float4*)(w3row + bkf);

    As[0][(akf + 0) * ALD + alr] = ftf32(av0.x);
    As[0][(akf + 1) * ALD + alr] = ftf32(av0.y);
    As[0][(akf + 2) * ALD + alr] = ftf32(av0.z);
    As[0][(akf + 3) * ALD + alr] = ftf32(av0.w);
    As[0][(akf + 4) * ALD + alr] = ftf32(av1.x);
    As[0][(akf + 5) * ALD + alr] = ftf32(av1.y);
    As[0][(akf + 6) * ALD + alr] = ftf32(av1.z);
    As[0][(akf + 7) * ALD + alr] = ftf32(av1.w);
    B1s[0][(bkf + 0) * BLD + blr] = ftf32(b1v.x);
    B1s[0][(bkf + 1) * BLD + blr] = ftf32(b1v.y);
    B1s[0][(bkf + 2) * BLD + blr] = ftf32(b1v.z);
    B1s[0][(bkf + 3) * BLD + blr] = ftf32(b1v.w);
    B3s[0][(bkf + 0) * BLD + blr] = ftf32(b3v.x);
    B3s[0][(bkf + 1) * BLD + blr] = ftf32(b3v.y);
    B3s[0][(bkf + 2) * BLD + blr] = ftf32(b3v.z);
    B3s[0][(bkf + 3) * BLD + blr] = ftf32(b3v.w);
    __syncthreads();

#pragma unroll 1
    for (int it = 0; it < DDIM / BK; it++) {
        int cur = it & 1, nxt = cur ^ 1;
        int k1 = (it + 1) * BK;
        if (k1 < DDIM) {
            av0 = *(const float4*)(xrow + k1 + akf);
            av1 = *(const float4*)(xrow + k1 + akf + 4);
            b1v = *(const float4*)(w1row + k1 + bkf);
            b3v = *(const float4*)(w3row + k1 + bkf);
        }
#pragma unroll
        for (int ks = 0; ks < BK; ks += 8) {
            uint32_t a[2][4];
#pragma unroll
            for (int i = 0; i < 2; i++) {
                int mrow = wm + i * 16 + g;
                a[i][0] = __float_as_uint(As[cur][(ks + tg)     * ALD + mrow]);
                a[i][1] = __float_as_uint(As[cur][(ks + tg)     * ALD + mrow + 8]);
                a[i][2] = __float_as_uint(As[cur][(ks + tg + 4) * ALD + mrow]);
                a[i][3] = __float_as_uint(As[cur][(ks + tg + 4) * ALD + mrow + 8]);
            }
#pragma unroll
            for (int j = 0; j < 4; j++) {
                int ncol = wn + j * 8 + g;
                uint32_t p0 = __float_as_uint(B1s[cur][(ks + tg)     * BLD + ncol]);
                uint32_t p1 = __float_as_uint(B1s[cur][(ks + tg + 4) * BLD + ncol]);
                uint32_t q0 = __float_as_uint(B3s[cur][(ks + tg)     * BLD + ncol]);
                uint32_t q1 = __float_as_uint(B3s[cur][(ks + tg + 4) * BLD + ncol]);
#pragma unroll
                for (int i = 0; i < 2; i++) {
                    mma_tf32(acc1[i][j], a[i][0], a[i][1], a[i][2], a[i][3], p0, p1);
                    mma_tf32(acc3[i][j], a[i][0], a[i][1], a[i][2], a[i][3], q0, q1);
                }
            }
        }
        if (k1 < DDIM) {
            As[nxt][(akf + 0) * ALD + alr] = ftf32(av0.x);
            As[nxt][(akf + 1) * ALD + alr] = ftf32(av0.y);
            As[nxt][(akf + 2) * ALD + alr] = ftf32(av0.z);
            As[nxt][(akf + 3) * ALD + alr] = ftf32(av0.w);
            As[nxt][(akf + 4) * ALD + alr] = ftf32(av1.x);
            As[nxt][(akf + 5) * ALD + alr] = ftf32(av1.y);
            As[nxt][(akf + 6) * ALD + alr] = ftf32(av1.z);
            As[nxt][(akf + 7) * ALD + alr] = ftf32(av1.w);
            B1s[nxt][(bkf + 0) * BLD + blr] = ftf32(b1v.x);
            B1s[nxt][(bkf + 1) * BLD + blr] = ftf32(b1v.y);
            B1s[nxt][(bkf + 2) * BLD + blr] = ftf32(b1v.z);
            B1s[nxt][(bkf + 3) * BLD + blr] = ftf32(b1v.w);
            B3s[nxt][(bkf + 0) * BLD + blr] = ftf32(b3v.x);
            B3s[nxt][(bkf + 1) * BLD + blr] = ftf32(b3v.y);
            B3s[nxt][(bkf + 2) * BLD + blr] = ftf32(b3v.z);
            B3s[nxt][(bkf + 3) * BLD + blr] = ftf32(b3v.w);
            __syncthreads();
        }
    }

    // epilogue: silu(acc1) * acc3 -> g_h
    int base = g_off[e];
#pragma unroll
    for (int i = 0; i < 2; i++) {
#pragma unroll
        for (int half = 0; half < 2; half++) {          // c0/c1 (row g), c2/c3 (row g+8)
            int mm = m0 + wm + i * 16 + g + half * 8;
            if (mm < cnt) {
                float* hrow = g_h + (size_t)(base + mm) * HDIM + j0 + wn;
#pragma unroll
                for (int j = 0; j < 4; j++) {
                    float v0 = acc1[i][j][half * 2 + 0];
                    float v1 = acc1[i][j][half * 2 + 1];
                    float2 o;
                    o.x = v0 / (1.f + __expf(-v0)) * acc3[i][j][half * 2 + 0];
                    o.y = v1 / (1.f + __expf(-v1)) * acc3[i][j][half * 2 + 1];
                    *(float2*)(hrow + j * 8 + tg * 2) = o;
                }
            }
        }
    }
}

// down-proj: g_part[r, d] = wgt * (h[r] . w2^T)   (no atomics)
__global__ __launch_bounds__(256, 2) void k_down(const float* __restrict__ w2) {
    int e   = blockIdx.z;
    int cnt = g_count[e];
    int m0  = blockIdx.x * BM;
    if (m0 >= cnt) return;
    int d0 = blockIdx.y * BN;

    __shared__ float As[2][BK * ALD];
    __shared__ float Bs[2][BK * BLD];

    int tid  = threadIdx.x;
    int lane = tid & 31;
    int warp = tid >> 5;
    int wm   = (warp >> 1) * 32;
    int wn   = (warp & 1) * 32;
    int g    = lane >> 2;
    int tg   = lane & 3;

    int alr = tid >> 1, akf = (tid & 1) * 8;
    int blr = tid >> 2, bkf = (tid & 3) * 4;

    int base = g_off[e];
    int am = m0 + alr;
    int amc = (am < cnt) ? am : (cnt - 1);
    const float* arow = g_h + (size_t)(base + amc) * HDIM;
    const float* brow = w2 + (size_t)e * DDIM * HDIM + (size_t)(d0 + blr) * HDIM;

    float acc[2][4][4];
#pragma unroll
    for (int i = 0; i < 2; i++)
#pragma unroll
        for (int j = 0; j < 4; j++)
#pragma unroll
            for (int c = 0; c < 4; c++) acc[i][j][c] = 0.f;

    float4 av0, av1, bv;
    av0 = *(const float4*)(arow + akf);
    av1 = *(const float4*)(arow + akf + 4);
    bv  = *(const float4*)(brow + bkf);

    As[0][(akf + 0) * ALD + alr] = ftf32(av0.x);
    As[0][(akf + 1) * ALD + alr] = ftf32(av0.y);
    As[0][(akf + 2) * ALD + alr] = ftf32(av0.z);
    As[0][(akf + 3) * ALD + alr] = ftf32(av0.w);
    As[0][(akf + 4) * ALD + alr] = ftf32(av1.x);
    As[0][(akf + 5) * ALD + alr] = ftf32(av1.y);
    As[0][(akf + 6) * ALD + alr] = ftf32(av1.z);
    As[0][(akf + 7) * ALD + alr] = ftf32(av1.w);
    Bs[0][(bkf + 0) * BLD + blr] = ftf32(bv.x);
    Bs[0][(bkf + 1) * BLD + blr] = ftf32(bv.y);
    Bs[0][(bkf + 2) * BLD + blr] = ftf32(bv.z);
    Bs[0][(bkf + 3) * BLD + blr] = ftf32(bv.w);
    __syncthreads();

#pragma unroll 1
    for (int it = 0; it < HDIM / BK; it++) {
        int cur = it & 1, nxt = cur ^ 1;
        int k1 = (it + 1) * BK;
        if (k1 < HDIM) {
            av0 = *(const float4*)(arow + k1 + akf);
            av1 = *(const float4*)(arow + k1 + akf + 4);
            bv  = *(const float4*)(brow + k1 + bkf);
        }
#pragma unroll
        for (int ks = 0; ks < BK; ks += 8) {
            uint32_t a[2][4];
#pragma unroll
            for (int i = 0; i < 2; i++) {
                int mrow = wm + i * 16 + g;
                a[i][0] = __float_as_uint(As[cur][(ks + tg)     * ALD + mrow]);
                a[i][1] = __float_as_uint(As[cur][(ks + tg)     * ALD + mrow + 8]);
                a[i][2] = __float_as_uint(As[cur][(ks + tg + 4) * ALD + mrow]);
                a[i][3] = __float_as_uint(As[cur][(ks + tg + 4) * ALD + mrow + 8]);
            }
#pragma unroll
            for (int j = 0; j < 4; j++) {
                int ncol = wn + j * 8 + g;
                uint32_t b0 = __float_as_uint(Bs[cur][(ks + tg)     * BLD + ncol]);
                uint32_t b1 = __float_as_uint(Bs[cur][(ks + tg + 4) * BLD + ncol]);
#pragma unroll
                for (int i = 0; i < 2; i++)
                    mma_tf32(acc[i][j], a[i][0], a[i][1], a[i][2], a[i][3], b0, b1);
            }
        }
        if (k1 < HDIM) {
            As[nxt][(akf + 0) * ALD + alr] = ftf32(av0.x);
            As[nxt][(akf + 1) * ALD + alr] = ftf32(av0.y);
            As[nxt][(akf + 2) * ALD + alr] = ftf32(av0.z);
            As[nxt][(akf + 3) * ALD + alr] = ftf32(av0.w);
            As[nxt][(akf + 4) * ALD + alr] = ftf32(av1.x);
            As[nxt][(akf + 5) * ALD + alr] = ftf32(av1.y);
            As[nxt][(akf + 6) * ALD + alr] = ftf32(av1.z);
            As[nxt][(akf + 7) * ALD + alr] = ftf32(av1.w);
            Bs[nxt][(bkf + 0) * BLD + blr] = ftf32(bv.x);
            Bs[nxt][(bkf + 1) * BLD + blr] = ftf32(bv.y);
            Bs[nxt][(bkf + 2) * BLD + blr] = ftf32(bv.z);
            Bs[nxt][(bkf + 3) * BLD + blr] = ftf32(bv.w);
            __syncthreads();
        }
    }

#pragma unroll
    for (int i = 0; i < 2; i++) {
#pragma unroll
        for (int half = 0; half < 2; half++) {
            int mm = m0 + wm + i * 16 + g + half * 8;
            if (mm < cnt) {
                float wg = g_wgt[e * NTOK + mm];
                float* prow = g_part + (size_t)(base + mm) * DDIM + d0 + wn;
#pragma unroll
                for (int j = 0; j < 4; j++) {
                    float2 o;
                    o.x = wg * acc[i][j][half * 2 + 0];
                    o.y = wg * acc[i][j][half * 2 + 1];
                    *(float2*)(prow + j * 8 + tg * 2) = o;
                }
            }
        }
    }
}

// gather: out[t] = part[r0] + part[r1]; 2 tokens per CTA
__global__ __launch_bounds__(256) void k_gather(float* __restrict__ out) {
    int t = blockIdx.x * 2 + (threadIdx.x >> 7);
    int i = threadIdx.x & 127;           // 128 threads x float4 = 512 floats
    int a0 = __ldg(&g_aslot[t * 2 + 0]);
    int a1 = __ldg(&g_aslot[t * 2 + 1]);
    int r0 = g_off[a0 >> 14] + (a0 & (NTOK - 1));
    int r1 = g_off[a1 >> 14] + (a1 & (NTOK - 1));
    float4 pa = *(const float4*)(g_part + (size_t)r0 * DDIM + i * 4);
    float4 pb = *(const float4*)(g_part + (size_t)r1 * DDIM + i * 4);
    float4 o;
    o.x = pa.x + pb.x; o.y = pa.y + pb.y;
    o.z = pa.z + pb.z; o.w = pa.w + pb.w;
    *(float4*)(out + (size_t)t * DDIM + i * 4) = o;
}

// ------------------------------------------------------------------
extern "C" void kernel_launch(void* const* d_in, const int* in_sizes, int n_in,
                              void* d_out, int out_size) {
    const float* x  = (const float*)d_in[0];
    const float* rw = (const float*)d_in[1];
    const float* w1 = (const float*)d_in[2];
    const float* w2 = (const float*)d_in[3];
    const float* w3 = (const float*)d_in[4];
    float* out = (float*)d_out;

    cudaMemsetAsync(out, 0, (size_t)out_size * sizeof(float), 0);
    k_zero<<<1, 32>>>();
    k_router<<<RBLK, 256>>>(x, rw);
    k_offs<<<1, 256>>>(out, out_size);

    dim3 gu(NTOK / BM, HDIM / BN, NEXP);   // 128 x 22 x 8, empty tiles early-exit
    k_up<<<gu, 256>>>(x, w1, w3);
    dim3 gd(NTOK / BM, DDIM / BN, NEXP);   // 128 x 8 x 8
    k_down<<<gd, 256>>>(w2);
    k_gather<<<NTOK / 2, 256>>>(out);
}

// round 16
// speedup vs baseline: 1.3026x; 1.3026x over previous
#include <cuda_runtime.h>
#include <math.h>
#include <stdint.h>

#define NEXP 8
#define TOPK 2
#define NTOK 16384
#define DDIM 512
#define HDIM 1408
#define MASSIGN (NTOK * TOPK)
#define RBLK (NTOK / 8)   // router blocks = 2048

// ---- scratch (device globals; no allocation) ----
__device__ int   g_count[NEXP];
__device__ int   g_off[NEXP + 1];
__device__ int   g_token[NEXP * NTOK];
__device__ float g_wgt[NEXP * NTOK];
__device__ int   g_aslot[NTOK * TOPK];           // (expert<<14)|slot per (token,k)
__device__ float g_usagep[RBLK * NEXP];          // per-router-block usage partials
__device__ float g_h[(size_t)MASSIGN * HDIM];    // ~184 MB hidden activations
__device__ float g_part[(size_t)MASSIGN * DDIM]; // ~64 MB weighted partial outputs

// ------------------------------------------------------------------
__device__ __forceinline__ uint32_t tfu(float x) {   // fp32 -> tf32 bits (RNA)
    uint32_t u;
    asm("cvt.rna.tf32.f32 %0, %1;" : "=r"(u) : "f"(x));
    return u;
}

__device__ __forceinline__ void mma_tf32(float c[4],
                                         uint32_t a0, uint32_t a1, uint32_t a2, uint32_t a3,
                                         uint32_t b0, uint32_t b1) {
    asm volatile(
        "mma.sync.aligned.m16n8k8.row.col.f32.tf32.tf32.f32 "
        "{%0,%1,%2,%3}, {%4,%5,%6,%7}, {%8,%9}, {%0,%1,%2,%3};\n"
        : "+f"(c[0]), "+f"(c[1]), "+f"(c[2]), "+f"(c[3])
        : "r"(a0), "r"(a1), "r"(a2), "r"(a3), "r"(b0), "r"(b1));
}

__device__ __forceinline__ void cp16(uint32_t dst, const void* src) {
    asm volatile("cp.async.cg.shared.global [%0], [%1], 16;"
                 :: "r"(dst), "l"(src) : "memory");
}
#define CP_COMMIT() asm volatile("cp.async.commit_group;" ::: "memory")
#define CP_WAIT1()  asm volatile("cp.async.wait_group 1;" ::: "memory")
#define CP_WAIT0()  asm volatile("cp.async.wait_group 0;" ::: "memory")

__device__ __forceinline__ uint32_t s2u(const void* p) {
    return (uint32_t)__cvta_generic_to_shared(p);
}

// ------------------------------------------------------------------
__global__ void k_zero() {
    int i = threadIdx.x;
    if (i < NEXP) g_count[i] = 0;
}

// ------------------------------------------------------------------
// Router: one warp per token. fp32 logits, softmax, top-2 (lowest index
// wins ties, matching lax.top_k), renormalize, scatter to expert lists.
// ------------------------------------------------------------------
__global__ void k_router(const float* __restrict__ x,
                         const float* __restrict__ rw) {
    int warp = threadIdx.x >> 5, lane = threadIdx.x & 31;
    int t = blockIdx.x * 8 + warp;
    __shared__ float susage[8][NEXP];

    float l[NEXP];
#pragma unroll
    for (int e = 0; e < NEXP; e++) l[e] = 0.f;

    const float* xr = x + (size_t)t * DDIM;
#pragma unroll 4
    for (int k = lane; k < DDIM; k += 32) {
        float xv = xr[k];
#pragma unroll
        for (int e = 0; e < NEXP; e++) l[e] += xv * rw[e * DDIM + k];
    }
#pragma unroll
    for (int o = 16; o > 0; o >>= 1)
#pragma unroll
        for (int e = 0; e < NEXP; e++)
            l[e] += __shfl_xor_sync(0xffffffffu, l[e], o);

    float mx = l[0];
#pragma unroll
    for (int e = 1; e < NEXP; e++) mx = fmaxf(mx, l[e]);
    float p[NEXP], s = 0.f;
#pragma unroll
    for (int e = 0; e < NEXP; e++) { p[e] = __expf(l[e] - mx); s += p[e]; }
    float inv = 1.f / s;
#pragma unroll
    for (int e = 0; e < NEXP; e++) p[e] *= inv;

    if (lane < NEXP) susage[warp][lane] = p[lane];

    if (lane == 0) {
        int i0 = 0;
#pragma unroll
        for (int e = 1; e < NEXP; e++) if (p[e] > p[i0]) i0 = e;
        int i1 = (i0 == 0) ? 1 : 0;
#pragma unroll
        for (int e = 0; e < NEXP; e++)
            if (e != i0 && p[e] > p[i1]) i1 = e;
        float sw = p[i0] + p[i1];
        float w0 = p[i0] / sw, w1 = p[i1] / sw;
        int s0 = atomicAdd(&g_count[i0], 1);
        g_token[i0 * NTOK + s0] = t; g_wgt[i0 * NTOK + s0] = w0;
        g_aslot[t * 2 + 0] = (i0 << 14) | s0;
        int s1 = atomicAdd(&g_count[i1], 1);
        g_token[i1 * NTOK + s1] = t; g_wgt[i1 * NTOK + s1] = w1;
        g_aslot[t * 2 + 1] = (i1 << 14) | s1;
    }
    __syncthreads();
    if (threadIdx.x < NEXP) {
        float u = 0.f;
#pragma unroll
        for (int w = 0; w < 8; w++) u += susage[w][threadIdx.x];   // fixed order
        g_usagep[blockIdx.x * NEXP + threadIdx.x] = u;
    }
}

// ------------------------------------------------------------------
// Offsets + aux loss (deterministic fixed-order reduction).
// ------------------------------------------------------------------
__global__ void k_offs(float* __restrict__ out, int out_size) {
    __shared__ float sus[NEXP];
    int tid = threadIdx.x, e = tid >> 5, lane = tid & 31;

    float u = 0.f;
    for (int b = lane; b < RBLK; b += 32)
        u += g_usagep[b * NEXP + e];
#pragma unroll
    for (int o = 16; o > 0; o >>= 1)
        u += __shfl_xor_sync(0xffffffffu, u, o);
    if (lane == 0) sus[e] = u;
    __syncthreads();

    if (tid == 0) {
        int acc = 0;
        for (int i = 0; i < NEXP; i++) { g_off[i] = acc; acc += g_count[i]; }
        g_off[NEXP] = acc;
        float a = 0.f;
        for (int i = 0; i < NEXP; i++) {
            float uu = sus[i] * (1.f / (float)NTOK);
            a += uu * uu;
        }
        out[out_size - 1] = (float)NEXP * a * 0.01f;
    }
}

// ------------------------------------------------------------------
// tf32 mma grouped GEMM, cp.async staging.
// BM=128, BN=64, BK=16, 256 thr = 8 warps (4M x 2N), warp tile 32x32.
// Smem row-major [row][k], pitch 20 floats: fragment gathers are
// bank-conflict-free (20g+tg mod 32 is a permutation of 0..31), and
// 80B row stride keeps every cp.async dst 16B-aligned.
// tf32 RNA conversion applied to fragments after LDS (idle fma pipe).
// ------------------------------------------------------------------
#define BM 128
#define BN 64
#define BK 16
#define KP 20    // smem k-pitch in floats (16 + 4 pad)

// up-proj: h[gm, j] = silu(x.w1^T) * (x.w3^T), per-expert token list
__global__ __launch_bounds__(256, 2) void k_up(const float* __restrict__ x,
                                               const float* __restrict__ w1,
                                               const float* __restrict__ w3) {
    int e   = blockIdx.z;
    int cnt = g_count[e];
    int m0  = blockIdx.x * BM;
    if (m0 >= cnt) return;
    int j0 = blockIdx.y * BN;

    __shared__ __align__(16) float As [2][BM * KP];
    __shared__ __align__(16) float B1s[2][BN * KP];
    __shared__ __align__(16) float B3s[2][BN * KP];

    int tid  = threadIdx.x;
    int lane = tid & 31;
    int warp = tid >> 5;
    int wm   = (warp >> 1) * 32;      // warp M offset
    int wn   = (warp & 1) * 32;       // warp N offset
    int g    = lane >> 2;             // 0..7
    int tg   = lane & 3;              // 0..3

    // loaders: 4 lanes per row (8 rows/warp -> 8 lines per LDG wavefront)
    int lr  = tid >> 2;               // 0..63
    int kco = (tid & 3) * 4;          // k sub-offset

    int am0 = m0 + lr, am1 = m0 + lr + 64;
    int t0 = (am0 < cnt) ? g_token[e * NTOK + am0] : g_token[e * NTOK];
    int t1 = (am1 < cnt) ? g_token[e * NTOK + am1] : g_token[e * NTOK];
    const float* xr0 = x + (size_t)t0 * DDIM + kco;
    const float* xr1 = x + (size_t)t1 * DDIM + kco;
    const float* w1r = w1 + (size_t)e * HDIM * DDIM + (size_t)(j0 + lr) * DDIM + kco;
    const float* w3r = w3 + (size_t)e * HDIM * DDIM + (size_t)(j0 + lr) * DDIM + kco;

    uint32_t dA0[2], dA1[2], dB1[2], dB3[2];
#pragma unroll
    for (int b = 0; b < 2; b++) {
        dA0[b] = s2u(&As[b][lr * KP + kco]);
        dA1[b] = s2u(&As[b][(lr + 64) * KP + kco]);
        dB1[b] = s2u(&B1s[b][lr * KP + kco]);
        dB3[b] = s2u(&B3s[b][lr * KP + kco]);
    }

    float acc1[2][4][4], acc3[2][4][4];
#pragma unroll
    for (int i = 0; i < 2; i++)
#pragma unroll
        for (int j = 0; j < 4; j++)
#pragma unroll
            for (int c = 0; c < 4; c++) { acc1[i][j][c] = 0.f; acc3[i][j][c] = 0.f; }

    // prologue: stage tile 0
    cp16(dA0[0], xr0); cp16(dA1[0], xr1);
    cp16(dB1[0], w1r); cp16(dB3[0], w3r);
    CP_COMMIT();

#pragma unroll 1
    for (int it = 0; it < DDIM / BK; it++) {
        int cur = it & 1;
        int k1 = (it + 1) * BK;
        if (k1 < DDIM) {
            int nxt = cur ^ 1;
            cp16(dA0[nxt], xr0 + k1); cp16(dA1[nxt], xr1 + k1);
            cp16(dB1[nxt], w1r + k1); cp16(dB3[nxt], w3r + k1);
            CP_COMMIT();
            CP_WAIT1();
        } else {
            CP_WAIT0();
        }
        __syncthreads();

#pragma unroll
        for (int ks = 0; ks < BK; ks += 8) {
            uint32_t a[2][4];
#pragma unroll
            for (int i = 0; i < 2; i++) {
                const float* Ar = &As[cur][(wm + i * 16 + g) * KP + ks + tg];
                a[i][0] = tfu(Ar[0]);
                a[i][1] = tfu(Ar[8 * KP]);
                a[i][2] = tfu(Ar[4]);
                a[i][3] = tfu(Ar[8 * KP + 4]);
            }
#pragma unroll
            for (int j = 0; j < 4; j++) {
                const float* B1r = &B1s[cur][(wn + j * 8 + g) * KP + ks + tg];
                const float* B3r = &B3s[cur][(wn + j * 8 + g) * KP + ks + tg];
                uint32_t p0 = tfu(B1r[0]), p1 = tfu(B1r[4]);
                uint32_t q0 = tfu(B3r[0]), q1 = tfu(B3r[4]);
#pragma unroll
                for (int i = 0; i < 2; i++) {
                    mma_tf32(acc1[i][j], a[i][0], a[i][1], a[i][2], a[i][3], p0, p1);
                    mma_tf32(acc3[i][j], a[i][0], a[i][1], a[i][2], a[i][3], q0, q1);
                }
            }
        }
        __syncthreads();
    }

    // epilogue: silu(acc1) * acc3 -> g_h
    int base = g_off[e];
#pragma unroll
    for (int i = 0; i < 2; i++) {
#pragma unroll
        for (int half = 0; half < 2; half++) {
            int mm = m0 + wm + i * 16 + g + half * 8;
            if (mm < cnt) {
                float* hrow = g_h + (size_t)(base + mm) * HDIM + j0 + wn;
#pragma unroll
                for (int j = 0; j < 4; j++) {
                    float v0 = acc1[i][j][half * 2 + 0];
                    float v1 = acc1[i][j][half * 2 + 1];
                    float2 o;
                    o.x = v0 / (1.f + __expf(-v0)) * acc3[i][j][half * 2 + 0];
                    o.y = v1 / (1.f + __expf(-v1)) * acc3[i][j][half * 2 + 1];
                    *(float2*)(hrow + j * 8 + tg * 2) = o;
                }
            }
        }
    }
}

// down-proj: g_part[r, d] = wgt * (h[r] . w2^T)   (no atomics)
__global__ __launch_bounds__(256, 3) void k_down(const float* __restrict__ w2) {
    int e   = blockIdx.z;
    int cnt = g_count[e];
    int m0  = blockIdx.x * BM;
    if (m0 >= cnt) return;
    int d0 = blockIdx.y * BN;

    __shared__ __align__(16) float As[2][BM * KP];
    __shared__ __align__(16) float Bs[2][BN * KP];

    int tid  = threadIdx.x;
    int lane = tid & 31;
    int warp = tid >> 5;
    int wm   = (warp >> 1) * 32;
    int wn   = (warp & 1) * 32;
    int g    = lane >> 2;
    int tg   = lane & 3;

    int lr  = tid >> 2;
    int kco = (tid & 3) * 4;

    int base = g_off[e];
    int am0 = m0 + lr, am1 = m0 + lr + 64;
    int r0 = base + ((am0 < cnt) ? am0 : (cnt - 1));
    int r1 = base + ((am1 < cnt) ? am1 : (cnt - 1));
    const float* ar0 = g_h + (size_t)r0 * HDIM + kco;
    const float* ar1 = g_h + (size_t)r1 * HDIM + kco;
    const float* br  = w2 + (size_t)e * DDIM * HDIM + (size_t)(d0 + lr) * HDIM + kco;

    uint32_t dA0[2], dA1[2], dB[2];
#pragma unroll
    for (int b = 0; b < 2; b++) {
        dA0[b] = s2u(&As[b][lr * KP + kco]);
        dA1[b] = s2u(&As[b][(lr + 64) * KP + kco]);
        dB[b]  = s2u(&Bs[b][lr * KP + kco]);
    }

    float acc[2][4][4];
#pragma unroll
    for (int i = 0; i < 2; i++)
#pragma unroll
        for (int j = 0; j < 4; j++)
#pragma unroll
            for (int c = 0; c < 4; c++) acc[i][j][c] = 0.f;

    cp16(dA0[0], ar0); cp16(dA1[0], ar1); cp16(dB[0], br);
    CP_COMMIT();

#pragma unroll 1
    for (int it = 0; it < HDIM / BK; it++) {
        int cur = it & 1;
        int k1 = (it + 1) * BK;
        if (k1 < HDIM) {
            int nxt = cur ^ 1;
            cp16(dA0[nxt], ar0 + k1); cp16(dA1[nxt], ar1 + k1); cp16(dB[nxt], br + k1);
            CP_COMMIT();
            CP_WAIT1();
        } else {
            CP_WAIT0();
        }
        __syncthreads();

#pragma unroll
        for (int ks = 0; ks < BK; ks += 8) {
            uint32_t a[2][4];
#pragma unroll
            for (int i = 0; i < 2; i++) {
                const float* Ar = &As[cur][(wm + i * 16 + g) * KP + ks + tg];
                a[i][0] = tfu(Ar[0]);
                a[i][1] = tfu(Ar[8 * KP]);
                a[i][2] = tfu(Ar[4]);
                a[i][3] = tfu(Ar[8 * KP + 4]);
            }
#pragma unroll
            for (int j = 0; j < 4; j++) {
                const float* Br = &Bs[cur][(wn + j * 8 + g) * KP + ks + tg];
                uint32_t b0 = tfu(Br[0]), b1 = tfu(Br[4]);
#pragma unroll
                for (int i = 0; i < 2; i++)
                    mma_tf32(acc[i][j], a[i][0], a[i][1], a[i][2], a[i][3], b0, b1);
            }
        }
        __syncthreads();
    }

#pragma unroll
    for (int i = 0; i < 2; i++) {
#pragma unroll
        for (int half = 0; half < 2; half++) {
            int mm = m0 + wm + i * 16 + g + half * 8;
            if (mm < cnt) {
                float wg = g_wgt[e * NTOK + mm];
                float* prow = g_part + (size_t)(base + mm) * DDIM + d0 + wn;
#pragma unroll
                for (int j = 0; j < 4; j++) {
                    float2 o;
                    o.x = wg * acc[i][j][half * 2 + 0];
                    o.y = wg * acc[i][j][half * 2 + 1];
                    *(float2*)(prow + j * 8 + tg * 2) = o;
                }
            }
        }
    }
}

// gather: out[t] = part[r0] + part[r1]; 2 tokens per CTA
__global__ __launch_bounds__(256) void k_gather(float* __restrict__ out) {
    int t = blockIdx.x * 2 + (threadIdx.x >> 7);
    int i = threadIdx.x & 127;
    int a0 = __ldg(&g_aslot[t * 2 + 0]);
    int a1 = __ldg(&g_aslot[t * 2 + 1]);
    int r0 = g_off[a0 >> 14] + (a0 & (NTOK - 1));
    int r1 = g_off[a1 >> 14] + (a1 & (NTOK - 1));
    float4 pa = *(const float4*)(g_part + (size_t)r0 * DDIM + i * 4);
    float4 pb = *(const float4*)(g_part + (size_t)r1 * DDIM + i * 4);
    float4 o;
    o.x = pa.x + pb.x; o.y = pa.y + pb.y;
    o.z = pa.z + pb.z; o.w = pa.w + pb.w;
    *(float4*)(out + (size_t)t * DDIM + i * 4) = o;
}

// ------------------------------------------------------------------
extern "C" void kernel_launch(void* const* d_in, const int* in_sizes, int n_in,
                              void* d_out, int out_size) {
    const float* x  = (const float*)d_in[0];
    const float* rw = (const float*)d_in[1];
    const float* w1 = (const float*)d_in[2];
    const float* w2 = (const float*)d_in[3];
    const float* w3 = (const float*)d_in[4];
    float* out = (float*)d_out;

    cudaMemsetAsync(out, 0, (size_t)out_size * sizeof(float), 0);
    k_zero<<<1, 32>>>();
    k_router<<<RBLK, 256>>>(x, rw);
    k_offs<<<1, 256>>>(out, out_size);

    dim3 gu(NTOK / BM, HDIM / BN, NEXP);   // 128 x 22 x 8, empty tiles early-exit
    k_up<<<gu, 256>>>(x, w1, w3);
    dim3 gd(NTOK / BM, DDIM / BN, NEXP);   // 128 x 8 x 8
    k_down<<<gd, 256>>>(w2);
    k_gather<<<NTOK / 2, 256>>>(out);
}